// round 1
// baseline (speedup 1.0000x reference)
#include <cuda_runtime.h>
#include <math.h>

#define NN      384
#define PAIRS   (NN*NN)          // 147456
#define IN_DIM  256
#define CLS_DIM 128
#define HID     512
#define OUT_DIM 256
#define FAN1    640
#define BN_EPS  1e-5f

// -------- device scratch (static __device__ arrays are the sanctioned scratch) -----
__device__ float g_H[(size_t)PAIRS * HID];       // lrelu output, pre-BN (BN folded into W2)
__device__ float g_Pi[NN * HID];                 // of[i] @ W1[:, :256].T + b1
__device__ float g_Pj[NN * HID];                 // of[j] @ W1[:, 256:512].T
__device__ float g_W1cT[CLS_DIM * HID];          // W1[:, 512:640] transposed -> [k][h]
__device__ float g_W2sT[HID * OUT_DIM];          // (W2 * s) transposed -> [h][o]
__device__ float g_b2p[OUT_DIM];                 // b2 + t @ W2.T

// ---------------- precompute kernels -----------------------------------------------

__global__ void precompute_pij(const float* __restrict__ of,
                               const float* __restrict__ W1,
                               const float* __restrict__ b1) {
    int idx = blockIdx.x * blockDim.x + threadIdx.x;   // 0 .. 2*NN*HID-1
    const int half = NN * HID;
    bool isPi = idx < half;
    int t = isPi ? idx : idx - half;
    int i = t / HID, h = t - (t / HID) * HID;
    const float* a = of + (size_t)i * IN_DIM;
    const float* w = W1 + (size_t)h * FAN1 + (isPi ? 0 : IN_DIM);
    float acc = 0.f;
#pragma unroll 8
    for (int k = 0; k < IN_DIM; k += 4) {
        float4 av = *(const float4*)(a + k);
        float4 wv = *(const float4*)(w + k);
        acc = fmaf(av.x, wv.x, acc);
        acc = fmaf(av.y, wv.y, acc);
        acc = fmaf(av.z, wv.z, acc);
        acc = fmaf(av.w, wv.w, acc);
    }
    if (isPi) g_Pi[t] = acc + b1[h];
    else      g_Pj[t] = acc;
}

__global__ void prep_w1ct(const float* __restrict__ W1) {
    int idx = blockIdx.x * blockDim.x + threadIdx.x;   // CLS_DIM*HID
    int k = idx / HID, h = idx - k * HID;
    g_W1cT[idx] = W1[(size_t)h * FAN1 + 512 + k];
}

__global__ void prep_w2st(const float* __restrict__ gamma,
                          const float* __restrict__ rv,
                          const float* __restrict__ W2) {
    int idx = blockIdx.x * blockDim.x + threadIdx.x;   // HID*OUT_DIM
    int h = idx / OUT_DIM, o = idx - h * OUT_DIM;
    float s = gamma[h] * rsqrtf(rv[h] + BN_EPS);
    g_W2sT[idx] = W2[(size_t)o * HID + h] * s;
}

__global__ void prep_b2p(const float* __restrict__ gamma,
                         const float* __restrict__ beta,
                         const float* __restrict__ rm,
                         const float* __restrict__ rv,
                         const float* __restrict__ W2,
                         const float* __restrict__ b2) {
    int o = threadIdx.x;                               // 256 threads
    float acc = b2[o];
    for (int h = 0; h < HID; h++) {
        float s = gamma[h] * rsqrtf(rv[h] + BN_EPS);
        float t = beta[h] - rm[h] * s;
        acc = fmaf(t, W2[(size_t)o * HID + h], acc);
    }
    g_b2p[o] = acc;
}

// ---------------- GEMM1: g_H = lrelu(cls @ W1c.T + Pi + Pj) ------------------------
// tile: BM=64 (pairs) x BN=64 (hid), K=128 in chunks of 64. 256 threads, 4x4/thread.

__global__ __launch_bounds__(256) void gemm1_kernel(const float* __restrict__ cls) {
    __shared__ float As[64][68];   // [m][k]  (+4 pad keeps float4 alignment & banks clean)
    __shared__ float Bs[64][64];   // [k][h]
    const int m0 = blockIdx.x * 64;
    const int h0 = blockIdx.y * 64;
    const int tid = threadIdx.x;
    const int tx = tid & 15;       // h quad
    const int ty = tid >> 4;       // m quad
    float acc[4][4];
#pragma unroll
    for (int r = 0; r < 4; r++)
#pragma unroll
        for (int c = 0; c < 4; c++) acc[r][c] = 0.f;

    for (int kc = 0; kc < CLS_DIM; kc += 64) {
#pragma unroll
        for (int it = 0; it < 4; it++) {
            int r = ty + it * 16;
            float4 v = *(const float4*)(cls + (size_t)(m0 + r) * CLS_DIM + kc + tx * 4);
            *(float4*)&As[r][tx * 4] = v;
            float4 w = *(const float4*)(g_W1cT + (size_t)(kc + r) * HID + h0 + tx * 4);
            *(float4*)&Bs[r][tx * 4] = w;
        }
        __syncthreads();
#pragma unroll 16
        for (int k = 0; k < 64; k++) {
            float4 b = *(const float4*)&Bs[k][tx * 4];
#pragma unroll
            for (int r = 0; r < 4; r++) {
                float a = As[ty * 4 + r][k];
                acc[r][0] = fmaf(a, b.x, acc[r][0]);
                acc[r][1] = fmaf(a, b.y, acc[r][1]);
                acc[r][2] = fmaf(a, b.z, acc[r][2]);
                acc[r][3] = fmaf(a, b.w, acc[r][3]);
            }
        }
        __syncthreads();
    }
#pragma unroll
    for (int r = 0; r < 4; r++) {
        int m = m0 + ty * 4 + r;
        int i = m / NN, j = m - i * NN;
        float4 pi = *(const float4*)(g_Pi + (size_t)i * HID + h0 + tx * 4);
        float4 pj = *(const float4*)(g_Pj + (size_t)j * HID + h0 + tx * 4);
        float4 o;
        o.x = acc[r][0] + pi.x + pj.x;
        o.y = acc[r][1] + pi.y + pj.y;
        o.z = acc[r][2] + pi.z + pj.z;
        o.w = acc[r][3] + pi.w + pj.w;
        o.x = o.x >= 0.f ? o.x : 0.01f * o.x;
        o.y = o.y >= 0.f ? o.y : 0.01f * o.y;
        o.z = o.z >= 0.f ? o.z : 0.01f * o.z;
        o.w = o.w >= 0.f ? o.w : 0.01f * o.w;
        *(float4*)(g_H + (size_t)m * HID + h0 + tx * 4) = o;
    }
}

// ---------------- GEMM2: F = g_H @ W2s.T + b2' -------------------------------------

__global__ __launch_bounds__(256) void gemm2_kernel(float* __restrict__ Fout) {
    __shared__ float As[64][68];   // [m][k]
    __shared__ float Bs[64][64];   // [k][o]
    const int m0 = blockIdx.x * 64;
    const int o0 = blockIdx.y * 64;
    const int tid = threadIdx.x;
    const int tx = tid & 15;
    const int ty = tid >> 4;
    float acc[4][4];
#pragma unroll
    for (int r = 0; r < 4; r++)
#pragma unroll
        for (int c = 0; c < 4; c++) acc[r][c] = 0.f;

    for (int kc = 0; kc < HID; kc += 64) {
#pragma unroll
        for (int it = 0; it < 4; it++) {
            int r = ty + it * 16;
            float4 v = *(const float4*)(g_H + (size_t)(m0 + r) * HID + kc + tx * 4);
            *(float4*)&As[r][tx * 4] = v;
            float4 w = *(const float4*)(g_W2sT + (size_t)(kc + r) * OUT_DIM + o0 + tx * 4);
            *(float4*)&Bs[r][tx * 4] = w;
        }
        __syncthreads();
#pragma unroll 16
        for (int k = 0; k < 64; k++) {
            float4 b = *(const float4*)&Bs[k][tx * 4];
#pragma unroll
            for (int r = 0; r < 4; r++) {
                float a = As[ty * 4 + r][k];
                acc[r][0] = fmaf(a, b.x, acc[r][0]);
                acc[r][1] = fmaf(a, b.y, acc[r][1]);
                acc[r][2] = fmaf(a, b.z, acc[r][2]);
                acc[r][3] = fmaf(a, b.w, acc[r][3]);
            }
        }
        __syncthreads();
    }
    float4 bb = *(const float4*)(g_b2p + o0 + tx * 4);
#pragma unroll
    for (int r = 0; r < 4; r++) {
        int m = m0 + ty * 4 + r;
        float4 o;
        o.x = acc[r][0] + bb.x;
        o.y = acc[r][1] + bb.y;
        o.z = acc[r][2] + bb.z;
        o.w = acc[r][3] + bb.w;
        *(float4*)(Fout + (size_t)m * OUT_DIM + o0 + tx * 4) = o;
    }
}

// ---------------- softmax over j + weighted pooling --------------------------------
// one block per i. logits[j] = F[i,j,:]·Wa  (ba dropped: softmax shift-invariant)

__global__ __launch_bounds__(256) void softmax_enhance(const float* __restrict__ F,
                                                       const float* __restrict__ Wa,
                                                       float* __restrict__ enhanced) {
    const int i = blockIdx.x;
    __shared__ float logit[NN];
    __shared__ float redm[8];
    __shared__ float reds[8];
    const int tid = threadIdx.x;
    const int lane = tid & 31, w = tid >> 5;

    // pass 1: logits, one j per warp round-robin
    for (int j = w; j < NN; j += 8) {
        const float* f = F + ((size_t)i * NN + j) * OUT_DIM;
        float p = 0.f;
        for (int o = lane; o < OUT_DIM; o += 32) p = fmaf(f[o], Wa[o], p);
#pragma unroll
        for (int s = 16; s; s >>= 1) p += __shfl_xor_sync(0xffffffffu, p, s);
        if (lane == 0) logit[j] = p;
    }
    __syncthreads();

    // max
    float m = -1e30f;
    for (int j = tid; j < NN; j += 256) m = fmaxf(m, logit[j]);
#pragma unroll
    for (int s = 16; s; s >>= 1) m = fmaxf(m, __shfl_xor_sync(0xffffffffu, m, s));
    if (lane == 0) redm[w] = m;
    __syncthreads();
    float M = fmaxf(fmaxf(fmaxf(redm[0], redm[1]), fmaxf(redm[2], redm[3])),
                    fmaxf(fmaxf(redm[4], redm[5]), fmaxf(redm[6], redm[7])));

    // exp + sum
    float sacc = 0.f;
    for (int j = tid; j < NN; j += 256) {
        float e = expf(logit[j] - M);
        logit[j] = e;
        sacc += e;
    }
#pragma unroll
    for (int s = 16; s; s >>= 1) sacc += __shfl_xor_sync(0xffffffffu, sacc, s);
    if (lane == 0) reds[w] = sacc;
    __syncthreads();
    float S = reds[0] + reds[1] + reds[2] + reds[3] + reds[4] + reds[5] + reds[6] + reds[7];
    float inv = 1.f / S;
    __syncthreads();   // logit[] fully written before pass 2 reads

    // pass 2: enhanced[i, o] = (1/S) * sum_j e_j * F[i,j,o]; thread = o
    const int o = tid;
    float acc = 0.f;
    const float* fb = F + (size_t)i * NN * OUT_DIM + o;
#pragma unroll 4
    for (int j = 0; j < NN; j++) acc = fmaf(logit[j], fb[(size_t)j * OUT_DIM], acc);
    enhanced[(size_t)i * OUT_DIM + o] = acc * inv;
}

// ---------------- launch -----------------------------------------------------------

extern "C" void kernel_launch(void* const* d_in, const int* in_sizes, int n_in,
                              void* d_out, int out_size) {
    const float* of    = (const float*)d_in[0];
    const float* cls   = (const float*)d_in[1];
    const float* W1    = (const float*)d_in[2];
    const float* b1    = (const float*)d_in[3];
    const float* gamma = (const float*)d_in[4];
    const float* beta  = (const float*)d_in[5];
    const float* rm    = (const float*)d_in[6];
    const float* rv    = (const float*)d_in[7];
    const float* W2    = (const float*)d_in[8];
    const float* b2    = (const float*)d_in[9];
    const float* Wa    = (const float*)d_in[10];
    // d_in[11] = ba: softmax shift-invariant, unused.

    float* out    = (float*)d_out;
    float* F      = out;                                   // [PAIRS, OUT]
    float* enh    = out + (size_t)PAIRS * OUT_DIM;         // [NN, OUT]
    float* clsout = enh + (size_t)NN * OUT_DIM;            // [PAIRS, CLS_DIM]

    // passthrough copy (independent, issue first)
    cudaMemcpyAsync(clsout, cls, (size_t)PAIRS * CLS_DIM * sizeof(float),
                    cudaMemcpyDeviceToDevice, 0);

    precompute_pij<<<(2 * NN * HID) / 256, 256>>>(of, W1, b1);
    prep_w1ct<<<(CLS_DIM * HID) / 256, 256>>>(W1);
    prep_w2st<<<(HID * OUT_DIM) / 256, 256>>>(gamma, rv, W2);
    prep_b2p<<<1, 256>>>(gamma, beta, rm, rv, W2, b2);

    dim3 g1(PAIRS / 64, HID / 64);
    gemm1_kernel<<<g1, 256>>>(cls);

    dim3 g2(PAIRS / 64, OUT_DIM / 64);
    gemm2_kernel<<<g2, 256>>>(F);

    softmax_enhance<<<NN, 256>>>(F, Wa, enh);
}

// round 4
// speedup vs baseline: 1.7799x; 1.7799x over previous
#include <cuda_runtime.h>
#include <cuda_bf16.h>
#include <stdint.h>
#include <math.h>

#define NN      384
#define PAIRS   (NN*NN)          // 147456
#define IN_DIM  256
#define CLS_DIM 128
#define HID     512
#define OUT_DIM 256
#define FAN1    640
#define BN_EPS  1e-5f

// ---------------- device scratch ---------------------------------------------------
__device__ __align__(16) float g_Pi[NN * HID];
__device__ __align__(16) float g_Pj[NN * HID];
__device__ __align__(16) float g_b2p[OUT_DIM];
__device__ __align__(16) __nv_bfloat16 g_Chi[(size_t)PAIRS * CLS_DIM];
__device__ __align__(16) __nv_bfloat16 g_Clo[(size_t)PAIRS * CLS_DIM];
__device__ __align__(16) __nv_bfloat16 g_W1hi[HID * CLS_DIM];
__device__ __align__(16) __nv_bfloat16 g_W1lo[HID * CLS_DIM];
__device__ __align__(16) __nv_bfloat16 g_W2hi[OUT_DIM * HID];
__device__ __align__(16) __nv_bfloat16 g_W2lo[OUT_DIM * HID];
__device__ __align__(16) __nv_bfloat16 g_Hhi[(size_t)PAIRS * HID];
__device__ __align__(16) __nv_bfloat16 g_Hlo[(size_t)PAIRS * HID];

// ---------------- helpers ----------------------------------------------------------

__device__ __forceinline__ uint32_t smem_u32(const void* p) {
    uint32_t a;
    asm("{ .reg .u64 t; cvta.to.shared.u64 t, %1; cvt.u32.u64 %0, t; }" : "=r"(a) : "l"(p));
    return a;
}

#define CP_ASYNC16(s, g) \
    asm volatile("cp.async.cg.shared.global [%0], [%1], 16;" :: "r"(s), "l"(g) : "memory")
#define CP_COMMIT()   asm volatile("cp.async.commit_group;" ::: "memory")
#define CP_WAIT(n)    asm volatile("cp.async.wait_group %0;" :: "n"(n) : "memory")

#define LDMATRIX_X4(r0, r1, r2, r3, addr) \
    asm volatile("ldmatrix.sync.aligned.m8n8.x4.shared.b16 {%0,%1,%2,%3}, [%4];" \
        : "=r"(r0), "=r"(r1), "=r"(r2), "=r"(r3) : "r"(addr))

#define MMA_BF16(c, a, b) \
    asm volatile("mma.sync.aligned.m16n8k16.row.col.f32.bf16.bf16.f32 " \
        "{%0,%1,%2,%3}, {%4,%5,%6,%7}, {%8,%9}, {%0,%1,%2,%3};" \
        : "+f"((c)[0]), "+f"((c)[1]), "+f"((c)[2]), "+f"((c)[3]) \
        : "r"((a)[0]), "r"((a)[1]), "r"((a)[2]), "r"((a)[3]), "r"((b)[0]), "r"((b)[1]))

__device__ __forceinline__ void split2(float v, __nv_bfloat16& h, __nv_bfloat16& l) {
    h = __float2bfloat16_rn(v);
    l = __float2bfloat16_rn(v - __bfloat162float(h));
}

// smem: 2 stages x (A 16KB + B 16KB) = 64KB. 128B rows, SW128 chunk swizzle.
#define STAGE_BYTES 32768
#define SMEM_GEMM   65536

// ---------------- precompute / conversion kernels ----------------------------------

__global__ void precompute_pij(const float* __restrict__ of,
                               const float* __restrict__ W1,
                               const float* __restrict__ b1) {
    int idx = blockIdx.x * blockDim.x + threadIdx.x;
    const int half = NN * HID;
    bool isPi = idx < half;
    int t = isPi ? idx : idx - half;
    int i = t / HID, h = t - (t / HID) * HID;
    const float* a = of + (size_t)i * IN_DIM;
    const float* w = W1 + (size_t)h * FAN1 + (isPi ? 0 : IN_DIM);
    float acc = 0.f;
#pragma unroll 8
    for (int k = 0; k < IN_DIM; k += 4) {
        float4 av = *(const float4*)(a + k);
        float4 wv = *(const float4*)(w + k);
        acc = fmaf(av.x, wv.x, acc);
        acc = fmaf(av.y, wv.y, acc);
        acc = fmaf(av.z, wv.z, acc);
        acc = fmaf(av.w, wv.w, acc);
    }
    if (isPi) g_Pi[t] = acc + b1[h];
    else      g_Pj[t] = acc;
}

__global__ void conv_cls(const float* __restrict__ cls) {
    size_t q = (size_t)blockIdx.x * 256 + threadIdx.x;
    float4 v = ((const float4*)cls)[q];
    __align__(8) __nv_bfloat16 hh[4], ll[4];
    split2(v.x, hh[0], ll[0]); split2(v.y, hh[1], ll[1]);
    split2(v.z, hh[2], ll[2]); split2(v.w, hh[3], ll[3]);
    *(uint2*)(g_Chi + q * 4) = *(uint2*)hh;
    *(uint2*)(g_Clo + q * 4) = *(uint2*)ll;
}

__global__ void conv_w1c(const float* __restrict__ W1) {
    int idx = blockIdx.x * 256 + threadIdx.x;                // HID*CLS_DIM
    int h = idx >> 7, k = idx & 127;
    float v = W1[(size_t)h * FAN1 + 512 + k];
    split2(v, g_W1hi[idx], g_W1lo[idx]);
}

__global__ void conv_w2s(const float* __restrict__ gamma,
                         const float* __restrict__ rv,
                         const float* __restrict__ W2) {
    int idx = blockIdx.x * 256 + threadIdx.x;                // OUT_DIM*HID
    int h = idx & (HID - 1);
    float s = gamma[h] * rsqrtf(rv[h] + BN_EPS);
    split2(W2[idx] * s, g_W2hi[idx], g_W2lo[idx]);
}

__global__ void prep_b2p(const float* __restrict__ gamma,
                         const float* __restrict__ beta,
                         const float* __restrict__ rm,
                         const float* __restrict__ rv,
                         const float* __restrict__ W2,
                         const float* __restrict__ b2) {
    __shared__ float red[4];
    int o = blockIdx.x, t = threadIdx.x;
    float acc = 0.f;
    for (int h = t; h < HID; h += 128) {
        float s = gamma[h] * rsqrtf(rv[h] + BN_EPS);
        acc = fmaf(beta[h] - rm[h] * s, W2[(size_t)o * HID + h], acc);
    }
#pragma unroll
    for (int s = 16; s; s >>= 1) acc += __shfl_xor_sync(0xffffffffu, acc, s);
    if ((t & 31) == 0) red[t >> 5] = acc;
    __syncthreads();
    if (t == 0) g_b2p[o] = red[0] + red[1] + red[2] + red[3] + b2[o];
}

// ---------------- GEMM1: H = lrelu(cls@W1c.T + Pi + Pj) -> split hi/lo -------------
// grid (PAIRS/128, HID/128), 256 thr, 8 warps (2m x 4n), warp tile 64x32.
// 3-term split over K=128 -> NITER = 6 chunks of BK=64.

__global__ __launch_bounds__(256) void gemm1_mma() {
    extern __shared__ char smem[];
    const uint32_t sb = smem_u32(smem);
    const int tid = threadIdx.x, lane = tid & 31, wid = tid >> 5;
    const int wm = wid & 1, wn = wid >> 1;
    const int m0 = blockIdx.x * 128, n0 = blockIdx.y * 128;

    const __nv_bfloat16* Aterm[3] = {g_Chi, g_Clo, g_Chi};
    const __nv_bfloat16* Bterm[3] = {g_W1hi, g_W1hi, g_W1lo};

    float acc[4][4][4];
#pragma unroll
    for (int a = 0; a < 4; a++)
#pragma unroll
        for (int b = 0; b < 4; b++)
#pragma unroll
            for (int c = 0; c < 4; c++) acc[a][b][c] = 0.f;

    const int NITER = 6;
#define G1_LOAD(iter, s) do {                                                         \
    const __nv_bfloat16* Ab = Aterm[(iter) >> 1];                                     \
    const __nv_bfloat16* Bb = Bterm[(iter) >> 1];                                     \
    int kc = ((iter) & 1) * 64;                                                       \
    uint32_t sa = sb + (s) * STAGE_BYTES;                                             \
    uint32_t sB = sa + 16384;                                                         \
    _Pragma("unroll")                                                                 \
    for (int it = 0; it < 4; ++it) {                                                  \
        int idx = tid + it * 256, r = idx >> 3, c = idx & 7;                          \
        uint32_t sw = r * 128 + ((c ^ (r & 7)) << 4);                                 \
        CP_ASYNC16(sa + sw, Ab + (size_t)(m0 + r) * CLS_DIM + kc + c * 8);            \
        CP_ASYNC16(sB + sw, Bb + (size_t)(n0 + r) * CLS_DIM + kc + c * 8);            \
    }                                                                                 \
} while (0)

    G1_LOAD(0, 0);
    CP_COMMIT();

    for (int iter = 0; iter < NITER; ++iter) {
        int s = iter & 1;
        if (iter + 1 < NITER) { G1_LOAD(iter + 1, s ^ 1); CP_COMMIT(); CP_WAIT(1); }
        else CP_WAIT(0);
        __syncthreads();

        uint32_t saw = sb + s * STAGE_BYTES + (wm * 64) * 128;
        uint32_t sbw = sb + s * STAGE_BYTES + 16384 + (wn * 32) * 128;
#pragma unroll
        for (int ks = 0; ks < 4; ++ks) {
            uint32_t b[4][2];
#pragma unroll
            for (int np = 0; np < 2; ++np) {
                int nrow = np * 16 + (lane & 7) + ((lane >> 4) << 3);
                int cc = ks * 2 + ((lane >> 3) & 1);
                uint32_t addr = sbw + nrow * 128 + ((cc ^ (nrow & 7)) << 4);
                LDMATRIX_X4(b[np * 2][0], b[np * 2][1], b[np * 2 + 1][0], b[np * 2 + 1][1], addr);
            }
#pragma unroll
            for (int mt = 0; mt < 4; ++mt) {
                int row = mt * 16 + (lane & 15);
                int cc = ks * 2 + (lane >> 4);
                uint32_t addr = saw + row * 128 + ((cc ^ (row & 7)) << 4);
                uint32_t a[4];
                LDMATRIX_X4(a[0], a[1], a[2], a[3], addr);
#pragma unroll
                for (int nt = 0; nt < 4; ++nt) MMA_BF16(acc[mt][nt], a, b[nt]);
            }
        }
        __syncthreads();
    }
#undef G1_LOAD

    // epilogue: + Pi + Pj, lrelu, split, store
#pragma unroll
    for (int mt = 0; mt < 4; ++mt) {
#pragma unroll
        for (int half = 0; half < 2; ++half) {
            int r = wm * 64 + mt * 16 + (lane >> 2) + half * 8;
            int m = m0 + r;
            int i = m / NN, j = m - (m / NN) * NN;
#pragma unroll
            for (int nt = 0; nt < 4; ++nt) {
                int h = n0 + wn * 32 + nt * 8 + 2 * (lane & 3);
                float2 pi = *(const float2*)(g_Pi + (size_t)i * HID + h);
                float2 pj = *(const float2*)(g_Pj + (size_t)j * HID + h);
                float v0 = acc[mt][nt][half * 2 + 0] + pi.x + pj.x;
                float v1 = acc[mt][nt][half * 2 + 1] + pi.y + pj.y;
                v0 = v0 >= 0.f ? v0 : 0.01f * v0;
                v1 = v1 >= 0.f ? v1 : 0.01f * v1;
                __align__(4) __nv_bfloat16 hh[2], ll[2];
                split2(v0, hh[0], ll[0]);
                split2(v1, hh[1], ll[1]);
                *(uint32_t*)(g_Hhi + (size_t)m * HID + h) = *(uint32_t*)hh;
                *(uint32_t*)(g_Hlo + (size_t)m * HID + h) = *(uint32_t*)ll;
            }
        }
    }
}

// ---------------- GEMM2: F = H @ (W2*s).T + b2' ------------------------------------
// grid (PAIRS/128, OUT/128). 3-term split over K=512 -> NITER = 24 chunks of 64.

__global__ __launch_bounds__(256) void gemm2_mma(float* __restrict__ F) {
    extern __shared__ char smem[];
    const uint32_t sb = smem_u32(smem);
    const int tid = threadIdx.x, lane = tid & 31, wid = tid >> 5;
    const int wm = wid & 1, wn = wid >> 1;
    const int m0 = blockIdx.x * 128, n0 = blockIdx.y * 128;

    const __nv_bfloat16* Aterm[3] = {g_Hhi, g_Hlo, g_Hhi};
    const __nv_bfloat16* Bterm[3] = {g_W2hi, g_W2hi, g_W2lo};

    float acc[4][4][4];
#pragma unroll
    for (int a = 0; a < 4; a++)
#pragma unroll
        for (int b = 0; b < 4; b++)
#pragma unroll
            for (int c = 0; c < 4; c++) acc[a][b][c] = 0.f;

    const int NITER = 24;
#define G2_LOAD(iter, s) do {                                                         \
    const __nv_bfloat16* Ab = Aterm[(iter) >> 3];                                     \
    const __nv_bfloat16* Bb = Bterm[(iter) >> 3];                                     \
    int kc = ((iter) & 7) * 64;                                                       \
    uint32_t sa = sb + (s) * STAGE_BYTES;                                             \
    uint32_t sB = sa + 16384;                                                         \
    _Pragma("unroll")                                                                 \
    for (int it = 0; it < 4; ++it) {                                                  \
        int idx = tid + it * 256, r = idx >> 3, c = idx & 7;                          \
        uint32_t sw = r * 128 + ((c ^ (r & 7)) << 4);                                 \
        CP_ASYNC16(sa + sw, Ab + (size_t)(m0 + r) * HID + kc + c * 8);                \
        CP_ASYNC16(sB + sw, Bb + (size_t)(n0 + r) * HID + kc + c * 8);                \
    }                                                                                 \
} while (0)

    G2_LOAD(0, 0);
    CP_COMMIT();

    for (int iter = 0; iter < NITER; ++iter) {
        int s = iter & 1;
        if (iter + 1 < NITER) { G2_LOAD(iter + 1, s ^ 1); CP_COMMIT(); CP_WAIT(1); }
        else CP_WAIT(0);
        __syncthreads();

        uint32_t saw = sb + s * STAGE_BYTES + (wm * 64) * 128;
        uint32_t sbw = sb + s * STAGE_BYTES + 16384 + (wn * 32) * 128;
#pragma unroll
        for (int ks = 0; ks < 4; ++ks) {
            uint32_t b[4][2];
#pragma unroll
            for (int np = 0; np < 2; ++np) {
                int nrow = np * 16 + (lane & 7) + ((lane >> 4) << 3);
                int cc = ks * 2 + ((lane >> 3) & 1);
                uint32_t addr = sbw + nrow * 128 + ((cc ^ (nrow & 7)) << 4);
                LDMATRIX_X4(b[np * 2][0], b[np * 2][1], b[np * 2 + 1][0], b[np * 2 + 1][1], addr);
            }
#pragma unroll
            for (int mt = 0; mt < 4; ++mt) {
                int row = mt * 16 + (lane & 15);
                int cc = ks * 2 + (lane >> 4);
                uint32_t addr = saw + row * 128 + ((cc ^ (row & 7)) << 4);
                uint32_t a[4];
                LDMATRIX_X4(a[0], a[1], a[2], a[3], addr);
#pragma unroll
                for (int nt = 0; nt < 4; ++nt) MMA_BF16(acc[mt][nt], a, b[nt]);
            }
        }
        __syncthreads();
    }
#undef G2_LOAD

#pragma unroll
    for (int mt = 0; mt < 4; ++mt) {
#pragma unroll
        for (int half = 0; half < 2; ++half) {
            int r = wm * 64 + mt * 16 + (lane >> 2) + half * 8;
            int m = m0 + r;
#pragma unroll
            for (int nt = 0; nt < 4; ++nt) {
                int o = n0 + wn * 32 + nt * 8 + 2 * (lane & 3);
                float2 bb = *(const float2*)(g_b2p + o);
                float2 v;
                v.x = acc[mt][nt][half * 2 + 0] + bb.x;
                v.y = acc[mt][nt][half * 2 + 1] + bb.y;
                *(float2*)(F + (size_t)m * OUT_DIM + o) = v;
            }
        }
    }
}

// ---------------- softmax over j + weighted pooling --------------------------------

__global__ __launch_bounds__(256) void softmax_enhance(const float* __restrict__ F,
                                                       const float* __restrict__ Wa,
                                                       float* __restrict__ enhanced) {
    const int i = blockIdx.x;
    __shared__ float logit[NN];
    __shared__ float redm[8];
    __shared__ float reds[8];
    const int tid = threadIdx.x;
    const int lane = tid & 31, w = tid >> 5;

    for (int j = w; j < NN; j += 8) {
        const float* f = F + ((size_t)i * NN + j) * OUT_DIM;
        float p = 0.f;
        for (int o = lane; o < OUT_DIM; o += 32) p = fmaf(f[o], Wa[o], p);
#pragma unroll
        for (int s = 16; s; s >>= 1) p += __shfl_xor_sync(0xffffffffu, p, s);
        if (lane == 0) logit[j] = p;
    }
    __syncthreads();

    float m = -1e30f;
    for (int j = tid; j < NN; j += 256) m = fmaxf(m, logit[j]);
#pragma unroll
    for (int s = 16; s; s >>= 1) m = fmaxf(m, __shfl_xor_sync(0xffffffffu, m, s));
    if (lane == 0) redm[w] = m;
    __syncthreads();
    float M = fmaxf(fmaxf(fmaxf(redm[0], redm[1]), fmaxf(redm[2], redm[3])),
                    fmaxf(fmaxf(redm[4], redm[5]), fmaxf(redm[6], redm[7])));

    float sacc = 0.f;
    for (int j = tid; j < NN; j += 256) {
        float e = expf(logit[j] - M);
        logit[j] = e;
        sacc += e;
    }
#pragma unroll
    for (int s = 16; s; s >>= 1) sacc += __shfl_xor_sync(0xffffffffu, sacc, s);
    if (lane == 0) reds[w] = sacc;
    __syncthreads();
    float S = reds[0] + reds[1] + reds[2] + reds[3] + reds[4] + reds[5] + reds[6] + reds[7];
    float inv = 1.f / S;
    __syncthreads();

    const int o = tid;
    float acc = 0.f;
    const float* fb = F + (size_t)i * NN * OUT_DIM + o;
#pragma unroll 4
    for (int j = 0; j < NN; j++) acc = fmaf(logit[j], fb[(size_t)j * OUT_DIM], acc);
    enhanced[(size_t)i * OUT_DIM + o] = acc * inv;
}

// ---------------- launch -----------------------------------------------------------

extern "C" void kernel_launch(void* const* d_in, const int* in_sizes, int n_in,
                              void* d_out, int out_size) {
    const float* of    = (const float*)d_in[0];
    const float* cls   = (const float*)d_in[1];
    const float* W1    = (const float*)d_in[2];
    const float* b1    = (const float*)d_in[3];
    const float* gamma = (const float*)d_in[4];
    const float* beta  = (const float*)d_in[5];
    const float* rm    = (const float*)d_in[6];
    const float* rv    = (const float*)d_in[7];
    const float* W2    = (const float*)d_in[8];
    const float* b2    = (const float*)d_in[9];
    const float* Wa    = (const float*)d_in[10];

    float* out    = (float*)d_out;
    float* F      = out;                                   // [PAIRS, OUT]
    float* enh    = out + (size_t)PAIRS * OUT_DIM;         // [NN, OUT]
    float* clsout = enh + (size_t)NN * OUT_DIM;            // [PAIRS, CLS_DIM]

    cudaFuncSetAttribute(gemm1_mma, cudaFuncAttributeMaxDynamicSharedMemorySize, SMEM_GEMM);
    cudaFuncSetAttribute(gemm2_mma, cudaFuncAttributeMaxDynamicSharedMemorySize, SMEM_GEMM);

    cudaMemcpyAsync(clsout, cls, (size_t)PAIRS * CLS_DIM * sizeof(float),
                    cudaMemcpyDeviceToDevice, 0);

    precompute_pij<<<(2 * NN * HID) / 256, 256>>>(of, W1, b1);
    conv_cls<<<(PAIRS * CLS_DIM / 4) / 256, 256>>>(cls);
    conv_w1c<<<(HID * CLS_DIM) / 256, 256>>>(W1);
    conv_w2s<<<(OUT_DIM * HID) / 256, 256>>>(gamma, rv, W2);
    prep_b2p<<<OUT_DIM, 128>>>(gamma, beta, rm, rv, W2, b2);

    dim3 g1(PAIRS / 128, HID / 128);
    gemm1_mma<<<g1, 256, SMEM_GEMM>>>();

    dim3 g2(PAIRS / 128, OUT_DIM / 128);
    gemm2_mma<<<g2, 256, SMEM_GEMM>>>(F);

    softmax_enhance<<<NN, 256>>>(F, Wa, enh);
}

// round 7
// speedup vs baseline: 1.8343x; 1.0306x over previous
#include <cuda_runtime.h>
#include <cuda_bf16.h>
#include <stdint.h>
#include <math.h>

#define NN      384
#define PAIRS   (NN*NN)          // 147456
#define IN_DIM  256
#define CLS_DIM 128
#define HID     512
#define OUT_DIM 256
#define FAN1    640
#define BN_EPS  1e-5f

// ---------------- device scratch ---------------------------------------------------
__device__ __align__(16) float g_Pi[NN * HID];
__device__ __align__(16) float g_Pj[NN * HID];
__device__ __align__(16) float g_b2p[OUT_DIM];
__device__ __align__(16) __nv_bfloat16 g_Chi[(size_t)PAIRS * CLS_DIM];
__device__ __align__(16) __nv_bfloat16 g_Clo[(size_t)PAIRS * CLS_DIM];
__device__ __align__(16) __nv_bfloat16 g_W1hi[HID * CLS_DIM];
__device__ __align__(16) __nv_bfloat16 g_W1lo[HID * CLS_DIM];
__device__ __align__(16) __nv_bfloat16 g_W2hi[OUT_DIM * HID];
__device__ __align__(16) __nv_bfloat16 g_W2lo[OUT_DIM * HID];
__device__ __align__(16) __nv_bfloat16 g_Hhi[(size_t)PAIRS * HID];
__device__ __align__(16) __nv_bfloat16 g_Hlo[(size_t)PAIRS * HID];

// ---------------- helpers ----------------------------------------------------------

__device__ __forceinline__ uint32_t smem_u32(const void* p) {
    uint32_t a;
    asm("{ .reg .u64 t; cvta.to.shared.u64 t, %1; cvt.u32.u64 %0, t; }" : "=r"(a) : "l"(p));
    return a;
}

#define CP_ASYNC16(s, g) \
    asm volatile("cp.async.cg.shared.global [%0], [%1], 16;" :: "r"(s), "l"(g) : "memory")
#define CP_COMMIT()   asm volatile("cp.async.commit_group;" ::: "memory")
#define CP_WAIT(n)    asm volatile("cp.async.wait_group %0;" :: "n"(n) : "memory")

#define LDMATRIX_X4(r0, r1, r2, r3, addr) \
    asm volatile("ldmatrix.sync.aligned.m8n8.x4.shared.b16 {%0,%1,%2,%3}, [%4];" \
        : "=r"(r0), "=r"(r1), "=r"(r2), "=r"(r3) : "r"(addr))

#define MMA_BF16(c, a, b) \
    asm volatile("mma.sync.aligned.m16n8k16.row.col.f32.bf16.bf16.f32 " \
        "{%0,%1,%2,%3}, {%4,%5,%6,%7}, {%8,%9}, {%0,%1,%2,%3};" \
        : "+f"((c)[0]), "+f"((c)[1]), "+f"((c)[2]), "+f"((c)[3]) \
        : "r"((a)[0]), "r"((a)[1]), "r"((a)[2]), "r"((a)[3]), "r"((b)[0]), "r"((b)[1]))

__device__ __forceinline__ void split2(float v, __nv_bfloat16& h, __nv_bfloat16& l) {
    h = __float2bfloat16_rn(v);
    l = __float2bfloat16_rn(v - __bfloat162float(h));
}

// smem: 2 stages x (Ahi 16K | Alo 16K | Bhi 16K | Blo 16K) = 128KB
#define TILE_BYTES  16384
#define STAGE_BYTES 65536
#define SMEM_GEMM   131072

// per-stage loader: 4 tiles of [128 rows x 64 bf16], SW128 chunk swizzle
#define LOAD_STAGE(sa, Ahi, Alo, Bhi, Blo, strideA, strideB, kc) do {                 \
    _Pragma("unroll")                                                                 \
    for (int it = 0; it < 4; ++it) {                                                  \
        int idx = tid + it * 256, r = idx >> 3, c = idx & 7;                          \
        uint32_t sw = r * 128 + ((c ^ (r & 7)) << 4);                                 \
        CP_ASYNC16((sa) + sw,                 (Ahi) + (size_t)(m0 + r) * (strideA) + (kc) + c * 8); \
        CP_ASYNC16((sa) + TILE_BYTES + sw,    (Alo) + (size_t)(m0 + r) * (strideA) + (kc) + c * 8); \
        CP_ASYNC16((sa) + 2*TILE_BYTES + sw,  (Bhi) + (size_t)(n0 + r) * (strideB) + (kc) + c * 8); \
        CP_ASYNC16((sa) + 3*TILE_BYTES + sw,  (Blo) + (size_t)(n0 + r) * (strideB) + (kc) + c * 8); \
    }                                                                                 \
} while (0)

// 3 term passes over one stage: (Ahi,Bhi), (Alo,Bhi), (Ahi,Blo) — same accumulator.
#define COMPUTE_STAGE(stage_base) do {                                                \
    _Pragma("unroll")                                                                 \
    for (int term = 0; term < 3; ++term) {                                            \
        uint32_t saw = (stage_base) + ((term == 1) ? TILE_BYTES : 0u) + (wm * 64) * 128; \
        uint32_t sbw = (stage_base) + ((term == 2) ? 3u*TILE_BYTES : 2u*TILE_BYTES) + (wn * 32) * 128; \
        _Pragma("unroll")                                                             \
        for (int ks = 0; ks < 4; ++ks) {                                              \
            uint32_t b[4][2];                                                         \
            _Pragma("unroll")                                                         \
            for (int np = 0; np < 2; ++np) {                                          \
                int nrow = np * 16 + (lane & 7) + ((lane >> 4) << 3);                 \
                int cc = ks * 2 + ((lane >> 3) & 1);                                  \
                uint32_t addr = sbw + nrow * 128 + ((cc ^ (nrow & 7)) << 4);          \
                LDMATRIX_X4(b[np*2][0], b[np*2][1], b[np*2+1][0], b[np*2+1][1], addr);\
            }                                                                         \
            _Pragma("unroll")                                                         \
            for (int mt = 0; mt < 4; ++mt) {                                          \
                int row = mt * 16 + (lane & 15);                                      \
                int cc = ks * 2 + (lane >> 4);                                        \
                uint32_t addr = saw + row * 128 + ((cc ^ (row & 7)) << 4);            \
                uint32_t a[4];                                                        \
                LDMATRIX_X4(a[0], a[1], a[2], a[3], addr);                            \
                _Pragma("unroll")                                                     \
                for (int nt = 0; nt < 4; ++nt) MMA_BF16(acc[mt][nt], a, b[nt]);       \
            }                                                                         \
        }                                                                             \
    }                                                                                 \
} while (0)

// ---------------- precompute / conversion kernels ----------------------------------

__global__ void precompute_pij(const float* __restrict__ of,
                               const float* __restrict__ W1,
                               const float* __restrict__ b1) {
    int idx = blockIdx.x * blockDim.x + threadIdx.x;
    const int half = NN * HID;
    bool isPi = idx < half;
    int t = isPi ? idx : idx - half;
    int i = t / HID, h = t - (t / HID) * HID;
    const float* a = of + (size_t)i * IN_DIM;
    const float* w = W1 + (size_t)h * FAN1 + (isPi ? 0 : IN_DIM);
    float acc = 0.f;
#pragma unroll 8
    for (int k = 0; k < IN_DIM; k += 4) {
        float4 av = *(const float4*)(a + k);
        float4 wv = *(const float4*)(w + k);
        acc = fmaf(av.x, wv.x, acc);
        acc = fmaf(av.y, wv.y, acc);
        acc = fmaf(av.z, wv.z, acc);
        acc = fmaf(av.w, wv.w, acc);
    }
    if (isPi) g_Pi[t] = acc + b1[h];
    else      g_Pj[t] = acc;
}

__global__ void conv_cls(const float* __restrict__ cls) {
    size_t q = (size_t)blockIdx.x * 256 + threadIdx.x;
    float4 v = ((const float4*)cls)[q];
    __align__(8) __nv_bfloat16 hh[4], ll[4];
    split2(v.x, hh[0], ll[0]); split2(v.y, hh[1], ll[1]);
    split2(v.z, hh[2], ll[2]); split2(v.w, hh[3], ll[3]);
    *(uint2*)(g_Chi + q * 4) = *(uint2*)hh;
    *(uint2*)(g_Clo + q * 4) = *(uint2*)ll;
}

__global__ void conv_w1c(const float* __restrict__ W1) {
    int idx = blockIdx.x * 256 + threadIdx.x;                // HID*CLS_DIM
    int h = idx >> 7, k = idx & 127;
    float v = W1[(size_t)h * FAN1 + 512 + k];
    split2(v, g_W1hi[idx], g_W1lo[idx]);
}

__global__ void conv_w2s(const float* __restrict__ gamma,
                         const float* __restrict__ rv,
                         const float* __restrict__ W2) {
    int idx = blockIdx.x * 256 + threadIdx.x;                // OUT_DIM*HID
    int h = idx & (HID - 1);
    float s = gamma[h] * rsqrtf(rv[h] + BN_EPS);
    split2(W2[idx] * s, g_W2hi[idx], g_W2lo[idx]);
}

__global__ void prep_b2p(const float* __restrict__ gamma,
                         const float* __restrict__ beta,
                         const float* __restrict__ rm,
                         const float* __restrict__ rv,
                         const float* __restrict__ W2,
                         const float* __restrict__ b2) {
    __shared__ float red[4];
    int o = blockIdx.x, t = threadIdx.x;
    float acc = 0.f;
    for (int h = t; h < HID; h += 128) {
        float s = gamma[h] * rsqrtf(rv[h] + BN_EPS);
        acc = fmaf(beta[h] - rm[h] * s, W2[(size_t)o * HID + h], acc);
    }
#pragma unroll
    for (int s = 16; s; s >>= 1) acc += __shfl_xor_sync(0xffffffffu, acc, s);
    if ((t & 31) == 0) red[t >> 5] = acc;
    __syncthreads();
    if (t == 0) g_b2p[o] = red[0] + red[1] + red[2] + red[3] + b2[o];
}

// ---------------- GEMM1: H = lrelu(cls@W1c.T + Pi + Pj) -> split hi/lo -------------
// grid (HID/128 = 4, PAIRS/128 = 1152): x = n-tile (fast) for A reuse via L2.
// term-interleaved: NITER = 2 K-chunks of 64, 3 MMA passes per chunk.

__global__ __launch_bounds__(256) void gemm1_mma() {
    extern __shared__ char smem[];
    const uint32_t sb = smem_u32(smem);
    const int tid = threadIdx.x, lane = tid & 31, wid = tid >> 5;
    const int wm = wid & 1, wn = wid >> 1;
    const int m0 = blockIdx.y * 128, n0 = blockIdx.x * 128;

    float acc[4][4][4];
#pragma unroll
    for (int a = 0; a < 4; a++)
#pragma unroll
        for (int b = 0; b < 4; b++)
#pragma unroll
            for (int c = 0; c < 4; c++) acc[a][b][c] = 0.f;

    LOAD_STAGE(sb, g_Chi, g_Clo, g_W1hi, g_W1lo, CLS_DIM, CLS_DIM, 0);
    CP_COMMIT();

#pragma unroll
    for (int iter = 0; iter < 2; ++iter) {
        uint32_t stage = sb + (iter & 1) * STAGE_BYTES;
        if (iter + 1 < 2) {
            uint32_t nstage = sb + ((iter + 1) & 1) * STAGE_BYTES;
            LOAD_STAGE(nstage, g_Chi, g_Clo, g_W1hi, g_W1lo, CLS_DIM, CLS_DIM, (iter + 1) * 64);
            CP_COMMIT();
            CP_WAIT(1);
        } else CP_WAIT(0);
        __syncthreads();
        COMPUTE_STAGE(stage);
        __syncthreads();
    }

    // epilogue: + Pi + Pj, lrelu, split, store
#pragma unroll
    for (int mt = 0; mt < 4; ++mt) {
#pragma unroll
        for (int half = 0; half < 2; ++half) {
            int r = wm * 64 + mt * 16 + (lane >> 2) + half * 8;
            int m = m0 + r;
            int i = m / NN, j = m - (m / NN) * NN;
#pragma unroll
            for (int nt = 0; nt < 4; ++nt) {
                int h = n0 + wn * 32 + nt * 8 + 2 * (lane & 3);
                float2 pi = *(const float2*)(g_Pi + (size_t)i * HID + h);
                float2 pj = *(const float2*)(g_Pj + (size_t)j * HID + h);
                float v0 = acc[mt][nt][half * 2 + 0] + pi.x + pj.x;
                float v1 = acc[mt][nt][half * 2 + 1] + pi.y + pj.y;
                v0 = v0 >= 0.f ? v0 : 0.01f * v0;
                v1 = v1 >= 0.f ? v1 : 0.01f * v1;
                __align__(4) __nv_bfloat16 hh[2], ll[2];
                split2(v0, hh[0], ll[0]);
                split2(v1, hh[1], ll[1]);
                *(uint32_t*)(g_Hhi + (size_t)m * HID + h) = *(uint32_t*)hh;
                *(uint32_t*)(g_Hlo + (size_t)m * HID + h) = *(uint32_t*)ll;
            }
        }
    }
}

// ---------------- GEMM2: F = H @ (W2*s).T + b2' ------------------------------------
// grid (OUT/128 = 2, PAIRS/128 = 1152). NITER = 8 K-chunks, 3 passes each.

__global__ __launch_bounds__(256) void gemm2_mma(float* __restrict__ F) {
    extern __shared__ char smem[];
    const uint32_t sb = smem_u32(smem);
    const int tid = threadIdx.x, lane = tid & 31, wid = tid >> 5;
    const int wm = wid & 1, wn = wid >> 1;
    const int m0 = blockIdx.y * 128, n0 = blockIdx.x * 128;

    float acc[4][4][4];
#pragma unroll
    for (int a = 0; a < 4; a++)
#pragma unroll
        for (int b = 0; b < 4; b++)
#pragma unroll
            for (int c = 0; c < 4; c++) acc[a][b][c] = 0.f;

    LOAD_STAGE(sb, g_Hhi, g_Hlo, g_W2hi, g_W2lo, HID, HID, 0);
    CP_COMMIT();

    for (int iter = 0; iter < 8; ++iter) {
        uint32_t stage = sb + (iter & 1) * STAGE_BYTES;
        if (iter + 1 < 8) {
            uint32_t nstage = sb + ((iter + 1) & 1) * STAGE_BYTES;
            LOAD_STAGE(nstage, g_Hhi, g_Hlo, g_W2hi, g_W2lo, HID, HID, (iter + 1) * 64);
            CP_COMMIT();
            CP_WAIT(1);
        } else CP_WAIT(0);
        __syncthreads();
        COMPUTE_STAGE(stage);
        __syncthreads();
    }

#pragma unroll
    for (int mt = 0; mt < 4; ++mt) {
#pragma unroll
        for (int half = 0; half < 2; ++half) {
            int r = wm * 64 + mt * 16 + (lane >> 2) + half * 8;
            int m = m0 + r;
#pragma unroll
            for (int nt = 0; nt < 4; ++nt) {
                int o = n0 + wn * 32 + nt * 8 + 2 * (lane & 3);
                float2 bb = *(const float2*)(g_b2p + o);
                float2 v;
                v.x = acc[mt][nt][half * 2 + 0] + bb.x;
                v.y = acc[mt][nt][half * 2 + 1] + bb.y;
                *(float2*)(F + (size_t)m * OUT_DIM + o) = v;
            }
        }
    }
}

// ---------------- softmax over j + weighted pooling --------------------------------

__global__ __launch_bounds__(256) void softmax_enhance(const float* __restrict__ F,
                                                       const float* __restrict__ Wa,
                                                       float* __restrict__ enhanced) {
    const int i = blockIdx.x;
    __shared__ float logit[NN];
    __shared__ float redm[8];
    __shared__ float reds[8];
    const int tid = threadIdx.x;
    const int lane = tid & 31, w = tid >> 5;

    for (int j = w; j < NN; j += 8) {
        const float* f = F + ((size_t)i * NN + j) * OUT_DIM;
        float p = 0.f;
        for (int o = lane; o < OUT_DIM; o += 32) p = fmaf(f[o], Wa[o], p);
#pragma unroll
        for (int s = 16; s; s >>= 1) p += __shfl_xor_sync(0xffffffffu, p, s);
        if (lane == 0) logit[j] = p;
    }
    __syncthreads();

    float m = -1e30f;
    for (int j = tid; j < NN; j += 256) m = fmaxf(m, logit[j]);
#pragma unroll
    for (int s = 16; s; s >>= 1) m = fmaxf(m, __shfl_xor_sync(0xffffffffu, m, s));
    if (lane == 0) redm[w] = m;
    __syncthreads();
    float M = fmaxf(fmaxf(fmaxf(redm[0], redm[1]), fmaxf(redm[2], redm[3])),
                    fmaxf(fmaxf(redm[4], redm[5]), fmaxf(redm[6], redm[7])));

    float sacc = 0.f;
    for (int j = tid; j < NN; j += 256) {
        float e = expf(logit[j] - M);
        logit[j] = e;
        sacc += e;
    }
#pragma unroll
    for (int s = 16; s; s >>= 1) sacc += __shfl_xor_sync(0xffffffffu, sacc, s);
    if (lane == 0) reds[w] = sacc;
    __syncthreads();
    float S = reds[0] + reds[1] + reds[2] + reds[3] + reds[4] + reds[5] + reds[6] + reds[7];
    float inv = 1.f / S;
    __syncthreads();

    const int o = tid;
    float acc = 0.f;
    const float* fb = F + (size_t)i * NN * OUT_DIM + o;
#pragma unroll 4
    for (int j = 0; j < NN; j++) acc = fmaf(logit[j], fb[(size_t)j * OUT_DIM], acc);
    enhanced[(size_t)i * OUT_DIM + o] = acc * inv;
}

// ---------------- launch -----------------------------------------------------------

extern "C" void kernel_launch(void* const* d_in, const int* in_sizes, int n_in,
                              void* d_out, int out_size) {
    const float* of    = (const float*)d_in[0];
    const float* cls   = (const float*)d_in[1];
    const float* W1    = (const float*)d_in[2];
    const float* b1    = (const float*)d_in[3];
    const float* gamma = (const float*)d_in[4];
    const float* beta  = (const float*)d_in[5];
    const float* rm    = (const float*)d_in[6];
    const float* rv    = (const float*)d_in[7];
    const float* W2    = (const float*)d_in[8];
    const float* b2    = (const float*)d_in[9];
    const float* Wa    = (const float*)d_in[10];

    float* out    = (float*)d_out;
    float* F      = out;                                   // [PAIRS, OUT]
    float* enh    = out + (size_t)PAIRS * OUT_DIM;         // [NN, OUT]
    float* clsout = enh + (size_t)NN * OUT_DIM;            // [PAIRS, CLS_DIM]

    cudaFuncSetAttribute(gemm1_mma, cudaFuncAttributeMaxDynamicSharedMemorySize, SMEM_GEMM);
    cudaFuncSetAttribute(gemm2_mma, cudaFuncAttributeMaxDynamicSharedMemorySize, SMEM_GEMM);

    cudaMemcpyAsync(clsout, cls, (size_t)PAIRS * CLS_DIM * sizeof(float),
                    cudaMemcpyDeviceToDevice, 0);

    precompute_pij<<<(2 * NN * HID) / 256, 256>>>(of, W1, b1);
    conv_cls<<<(PAIRS * CLS_DIM / 4) / 256, 256>>>(cls);
    conv_w1c<<<(HID * CLS_DIM) / 256, 256>>>(W1);
    conv_w2s<<<(OUT_DIM * HID) / 256, 256>>>(gamma, rv, W2);
    prep_b2p<<<OUT_DIM, 128>>>(gamma, beta, rm, rv, W2, b2);

    dim3 g1(HID / 128, PAIRS / 128);        // x = n-tile (fast), y = m-tile
    gemm1_mma<<<g1, 256, SMEM_GEMM>>>();

    dim3 g2(OUT_DIM / 128, PAIRS / 128);
    gemm2_mma<<<g2, 256, SMEM_GEMM>>>(F);

    softmax_enhance<<<NN, 256>>>(F, Wa, enh);
}

// round 8
// speedup vs baseline: 2.4686x; 1.3458x over previous
#include <cuda_runtime.h>
#include <cuda_fp16.h>
#include <stdint.h>
#include <math.h>

#define NN      384
#define PAIRS   (NN*NN)          // 147456
#define IN_DIM  256
#define CLS_DIM 128
#define HID     512
#define OUT_DIM 256
#define FAN1    640
#define BN_EPS  1e-5f

// ---------------- device scratch ---------------------------------------------------
__device__ __align__(16) float g_Pi[NN * HID];
__device__ __align__(16) float g_Pj[NN * HID];
__device__ __align__(16) float g_b2p[OUT_DIM];
__device__ __align__(16) __half g_Chi[(size_t)PAIRS * CLS_DIM];   // cls hi (fp16)
__device__ __align__(16) __half g_Clo[(size_t)PAIRS * CLS_DIM];   // cls lo (fp16)
__device__ __align__(16) __half g_W1h[HID * CLS_DIM];             // W1c fp16 (single)
__device__ __align__(16) __half g_W2h[OUT_DIM * HID];             // (W2*s) fp16 (single)
__device__ __align__(16) __half g_Hhi[(size_t)PAIRS * HID];       // lrelu(H) hi
__device__ __align__(16) __half g_Hlo[(size_t)PAIRS * HID];       // lrelu(H) lo

// ---------------- helpers ----------------------------------------------------------

__device__ __forceinline__ uint32_t smem_u32(const void* p) {
    uint32_t a;
    asm("{ .reg .u64 t; cvta.to.shared.u64 t, %1; cvt.u32.u64 %0, t; }" : "=r"(a) : "l"(p));
    return a;
}

#define CP_ASYNC16(s, g) \
    asm volatile("cp.async.cg.shared.global [%0], [%1], 16;" :: "r"(s), "l"(g) : "memory")
#define CP_COMMIT()   asm volatile("cp.async.commit_group;" ::: "memory")
#define CP_WAIT(n)    asm volatile("cp.async.wait_group %0;" :: "n"(n) : "memory")

#define LDMATRIX_X4(r0, r1, r2, r3, addr) \
    asm volatile("ldmatrix.sync.aligned.m8n8.x4.shared.b16 {%0,%1,%2,%3}, [%4];" \
        : "=r"(r0), "=r"(r1), "=r"(r2), "=r"(r3) : "r"(addr))

#define MMA_F16(c, a, b) \
    asm volatile("mma.sync.aligned.m16n8k16.row.col.f32.f16.f16.f32 " \
        "{%0,%1,%2,%3}, {%4,%5,%6,%7}, {%8,%9}, {%0,%1,%2,%3};" \
        : "+f"((c)[0]), "+f"((c)[1]), "+f"((c)[2]), "+f"((c)[3]) \
        : "r"((a)[0]), "r"((a)[1]), "r"((a)[2]), "r"((a)[3]), "r"((b)[0]), "r"((b)[1]))

__device__ __forceinline__ void split2h(float v, __half& h, __half& l) {
    h = __float2half_rn(v);
    l = __float2half_rn(v - __half2float(h));
}

// smem: 2 stages x (Ahi 16K | Alo 16K | Bh 16K) = 96KB -> 2 CTAs/SM
#define TILE_BYTES  16384
#define STAGE_BYTES 49152
#define SMEM_GEMM   98304

// per-stage loader: 3 tiles of [128 rows x 64 fp16], SW128 chunk swizzle
#define LOAD_STAGE(sa, Ahi, Alo, Bh, strideA, strideB, kc) do {                       \
    _Pragma("unroll")                                                                 \
    for (int it = 0; it < 4; ++it) {                                                  \
        int idx = tid + it * 256, r = idx >> 3, c = idx & 7;                          \
        uint32_t sw = r * 128 + ((c ^ (r & 7)) << 4);                                 \
        CP_ASYNC16((sa) + sw,                (Ahi) + (size_t)(m0 + r) * (strideA) + (kc) + c * 8); \
        CP_ASYNC16((sa) + TILE_BYTES + sw,   (Alo) + (size_t)(m0 + r) * (strideA) + (kc) + c * 8); \
        CP_ASYNC16((sa) + 2*TILE_BYTES + sw, (Bh)  + (size_t)(n0 + r) * (strideB) + (kc) + c * 8); \
    }                                                                                 \
} while (0)

// 2 term passes over one stage: (Ahi,Bh), (Alo,Bh) — same accumulator.
#define COMPUTE_STAGE(stage_base) do {                                                \
    _Pragma("unroll")                                                                 \
    for (int term = 0; term < 2; ++term) {                                            \
        uint32_t saw = (stage_base) + term * TILE_BYTES + (wm * 64) * 128;            \
        uint32_t sbw = (stage_base) + 2u * TILE_BYTES + (wn * 32) * 128;              \
        _Pragma("unroll")                                                             \
        for (int ks = 0; ks < 4; ++ks) {                                              \
            uint32_t b[4][2];                                                         \
            _Pragma("unroll")                                                         \
            for (int np = 0; np < 2; ++np) {                                          \
                int nrow = np * 16 + (lane & 7) + ((lane >> 4) << 3);                 \
                int cc = ks * 2 + ((lane >> 3) & 1);                                  \
                uint32_t addr = sbw + nrow * 128 + ((cc ^ (nrow & 7)) << 4);          \
                LDMATRIX_X4(b[np*2][0], b[np*2][1], b[np*2+1][0], b[np*2+1][1], addr);\
            }                                                                         \
            _Pragma("unroll")                                                         \
            for (int mt = 0; mt < 4; ++mt) {                                          \
                int row = mt * 16 + (lane & 15);                                      \
                int cc = ks * 2 + (lane >> 4);                                        \
                uint32_t addr = saw + row * 128 + ((cc ^ (row & 7)) << 4);            \
                uint32_t a[4];                                                        \
                LDMATRIX_X4(a[0], a[1], a[2], a[3], addr);                            \
                _Pragma("unroll")                                                     \
                for (int nt = 0; nt < 4; ++nt) MMA_F16(acc[mt][nt], a, b[nt]);        \
            }                                                                         \
        }                                                                             \
    }                                                                                 \
} while (0)

// ---------------- precompute / conversion kernels ----------------------------------

__global__ void precompute_pij(const float* __restrict__ of,
                               const float* __restrict__ W1,
                               const float* __restrict__ b1) {
    int idx = blockIdx.x * blockDim.x + threadIdx.x;
    const int half = NN * HID;
    bool isPi = idx < half;
    int t = isPi ? idx : idx - half;
    int i = t / HID, h = t - (t / HID) * HID;
    const float* a = of + (size_t)i * IN_DIM;
    const float* w = W1 + (size_t)h * FAN1 + (isPi ? 0 : IN_DIM);
    float acc = 0.f;
#pragma unroll 8
    for (int k = 0; k < IN_DIM; k += 4) {
        float4 av = *(const float4*)(a + k);
        float4 wv = *(const float4*)(w + k);
        acc = fmaf(av.x, wv.x, acc);
        acc = fmaf(av.y, wv.y, acc);
        acc = fmaf(av.z, wv.z, acc);
        acc = fmaf(av.w, wv.w, acc);
    }
    if (isPi) g_Pi[t] = acc + b1[h];
    else      g_Pj[t] = acc;
}

__global__ void conv_cls(const float* __restrict__ cls) {
    size_t q = (size_t)blockIdx.x * 256 + threadIdx.x;       // quad of 4 floats
    float4 v = ((const float4*)cls)[q];
    __align__(8) __half hh[4], ll[4];
    split2h(v.x, hh[0], ll[0]); split2h(v.y, hh[1], ll[1]);
    split2h(v.z, hh[2], ll[2]); split2h(v.w, hh[3], ll[3]);
    *(uint2*)(g_Chi + q * 4) = *(uint2*)hh;
    *(uint2*)(g_Clo + q * 4) = *(uint2*)ll;
}

__global__ void conv_w1c(const float* __restrict__ W1) {
    int idx = blockIdx.x * 256 + threadIdx.x;                // HID*CLS_DIM
    int h = idx >> 7, k = idx & 127;
    g_W1h[idx] = __float2half_rn(W1[(size_t)h * FAN1 + 512 + k]);
}

__global__ void conv_w2s(const float* __restrict__ gamma,
                         const float* __restrict__ rv,
                         const float* __restrict__ W2) {
    int idx = blockIdx.x * 256 + threadIdx.x;                // OUT_DIM*HID
    int h = idx & (HID - 1);
    float s = gamma[h] * rsqrtf(rv[h] + BN_EPS);
    g_W2h[idx] = __float2half_rn(W2[idx] * s);
}

__global__ void prep_b2p(const float* __restrict__ gamma,
                         const float* __restrict__ beta,
                         const float* __restrict__ rm,
                         const float* __restrict__ rv,
                         const float* __restrict__ W2,
                         const float* __restrict__ b2) {
    __shared__ float red[4];
    int o = blockIdx.x, t = threadIdx.x;
    float acc = 0.f;
    for (int h = t; h < HID; h += 128) {
        float s = gamma[h] * rsqrtf(rv[h] + BN_EPS);
        acc = fmaf(beta[h] - rm[h] * s, W2[(size_t)o * HID + h], acc);
    }
#pragma unroll
    for (int s = 16; s; s >>= 1) acc += __shfl_xor_sync(0xffffffffu, acc, s);
    if ((t & 31) == 0) red[t >> 5] = acc;
    __syncthreads();
    if (t == 0) g_b2p[o] = red[0] + red[1] + red[2] + red[3] + b2[o];
}

// ---------------- GEMM1: H = lrelu(cls@W1c.T + Pi + Pj) -> split hi/lo (fp16) ------
// grid (HID/128 = 4, PAIRS/128 = 1152). 2 K-chunks of 64, 2 term passes per chunk.

__global__ __launch_bounds__(256) void gemm1_mma() {
    extern __shared__ char smem[];
    const uint32_t sb = smem_u32(smem);
    const int tid = threadIdx.x, lane = tid & 31, wid = tid >> 5;
    const int wm = wid & 1, wn = wid >> 1;
    const int m0 = blockIdx.y * 128, n0 = blockIdx.x * 128;

    float acc[4][4][4];
#pragma unroll
    for (int a = 0; a < 4; a++)
#pragma unroll
        for (int b = 0; b < 4; b++)
#pragma unroll
            for (int c = 0; c < 4; c++) acc[a][b][c] = 0.f;

    LOAD_STAGE(sb, g_Chi, g_Clo, g_W1h, CLS_DIM, CLS_DIM, 0);
    CP_COMMIT();

#pragma unroll
    for (int iter = 0; iter < 2; ++iter) {
        uint32_t stage = sb + (iter & 1) * STAGE_BYTES;
        if (iter + 1 < 2) {
            uint32_t nstage = sb + ((iter + 1) & 1) * STAGE_BYTES;
            LOAD_STAGE(nstage, g_Chi, g_Clo, g_W1h, CLS_DIM, CLS_DIM, (iter + 1) * 64);
            CP_COMMIT();
            CP_WAIT(1);
        } else CP_WAIT(0);
        __syncthreads();
        COMPUTE_STAGE(stage);
        __syncthreads();
    }

    // epilogue: + Pi + Pj, lrelu, split to fp16 hi/lo, store
#pragma unroll
    for (int mt = 0; mt < 4; ++mt) {
#pragma unroll
        for (int half = 0; half < 2; ++half) {
            int r = wm * 64 + mt * 16 + (lane >> 2) + half * 8;
            int m = m0 + r;
            int i = m / NN, j = m - (m / NN) * NN;
#pragma unroll
            for (int nt = 0; nt < 4; ++nt) {
                int h = n0 + wn * 32 + nt * 8 + 2 * (lane & 3);
                float2 pi = *(const float2*)(g_Pi + (size_t)i * HID + h);
                float2 pj = *(const float2*)(g_Pj + (size_t)j * HID + h);
                float v0 = acc[mt][nt][half * 2 + 0] + pi.x + pj.x;
                float v1 = acc[mt][nt][half * 2 + 1] + pi.y + pj.y;
                v0 = v0 >= 0.f ? v0 : 0.01f * v0;
                v1 = v1 >= 0.f ? v1 : 0.01f * v1;
                __align__(4) __half hh[2], ll[2];
                split2h(v0, hh[0], ll[0]);
                split2h(v1, hh[1], ll[1]);
                *(uint32_t*)(g_Hhi + (size_t)m * HID + h) = *(uint32_t*)hh;
                *(uint32_t*)(g_Hlo + (size_t)m * HID + h) = *(uint32_t*)ll;
            }
        }
    }
}

// ---------------- GEMM2: F = H @ (W2*s).T + b2' ------------------------------------
// grid (OUT/128 = 2, PAIRS/128 = 1152). 8 K-chunks, 2 term passes each.

__global__ __launch_bounds__(256) void gemm2_mma(float* __restrict__ F) {
    extern __shared__ char smem[];
    const uint32_t sb = smem_u32(smem);
    const int tid = threadIdx.x, lane = tid & 31, wid = tid >> 5;
    const int wm = wid & 1, wn = wid >> 1;
    const int m0 = blockIdx.y * 128, n0 = blockIdx.x * 128;

    float acc[4][4][4];
#pragma unroll
    for (int a = 0; a < 4; a++)
#pragma unroll
        for (int b = 0; b < 4; b++)
#pragma unroll
            for (int c = 0; c < 4; c++) acc[a][b][c] = 0.f;

    LOAD_STAGE(sb, g_Hhi, g_Hlo, g_W2h, HID, HID, 0);
    CP_COMMIT();

    for (int iter = 0; iter < 8; ++iter) {
        uint32_t stage = sb + (iter & 1) * STAGE_BYTES;
        if (iter + 1 < 8) {
            uint32_t nstage = sb + ((iter + 1) & 1) * STAGE_BYTES;
            LOAD_STAGE(nstage, g_Hhi, g_Hlo, g_W2h, HID, HID, (iter + 1) * 64);
            CP_COMMIT();
            CP_WAIT(1);
        } else CP_WAIT(0);
        __syncthreads();
        COMPUTE_STAGE(stage);
        __syncthreads();
    }

#pragma unroll
    for (int mt = 0; mt < 4; ++mt) {
#pragma unroll
        for (int half = 0; half < 2; ++half) {
            int r = wm * 64 + mt * 16 + (lane >> 2) + half * 8;
            int m = m0 + r;
#pragma unroll
            for (int nt = 0; nt < 4; ++nt) {
                int o = n0 + wn * 32 + nt * 8 + 2 * (lane & 3);
                float2 bb = *(const float2*)(g_b2p + o);
                float2 v;
                v.x = acc[mt][nt][half * 2 + 0] + bb.x;
                v.y = acc[mt][nt][half * 2 + 1] + bb.y;
                *(float2*)(F + (size_t)m * OUT_DIM + o) = v;
            }
        }
    }
}

// ---------------- softmax over j + weighted pooling --------------------------------

__global__ __launch_bounds__(256) void softmax_enhance(const float* __restrict__ F,
                                                       const float* __restrict__ Wa,
                                                       float* __restrict__ enhanced) {
    const int i = blockIdx.x;
    __shared__ float logit[NN];
    __shared__ float redm[8];
    __shared__ float reds[8];
    const int tid = threadIdx.x;
    const int lane = tid & 31, w = tid >> 5;

    for (int j = w; j < NN; j += 8) {
        const float* f = F + ((size_t)i * NN + j) * OUT_DIM;
        float p = 0.f;
        for (int o = lane; o < OUT_DIM; o += 32) p = fmaf(f[o], Wa[o], p);
#pragma unroll
        for (int s = 16; s; s >>= 1) p += __shfl_xor_sync(0xffffffffu, p, s);
        if (lane == 0) logit[j] = p;
    }
    __syncthreads();

    float m = -1e30f;
    for (int j = tid; j < NN; j += 256) m = fmaxf(m, logit[j]);
#pragma unroll
    for (int s = 16; s; s >>= 1) m = fmaxf(m, __shfl_xor_sync(0xffffffffu, m, s));
    if (lane == 0) redm[w] = m;
    __syncthreads();
    float M = fmaxf(fmaxf(fmaxf(redm[0], redm[1]), fmaxf(redm[2], redm[3])),
                    fmaxf(fmaxf(redm[4], redm[5]), fmaxf(redm[6], redm[7])));

    float sacc = 0.f;
    for (int j = tid; j < NN; j += 256) {
        float e = expf(logit[j] - M);
        logit[j] = e;
        sacc += e;
    }
#pragma unroll
    for (int s = 16; s; s >>= 1) sacc += __shfl_xor_sync(0xffffffffu, sacc, s);
    if (lane == 0) reds[w] = sacc;
    __syncthreads();
    float S = reds[0] + reds[1] + reds[2] + reds[3] + reds[4] + reds[5] + reds[6] + reds[7];
    float inv = 1.f / S;
    __syncthreads();

    const int o = tid;
    float acc = 0.f;
    const float* fb = F + (size_t)i * NN * OUT_DIM + o;
#pragma unroll 4
    for (int j = 0; j < NN; j++) acc = fmaf(logit[j], fb[(size_t)j * OUT_DIM], acc);
    enhanced[(size_t)i * OUT_DIM + o] = acc * inv;
}

// ---------------- launch -----------------------------------------------------------

extern "C" void kernel_launch(void* const* d_in, const int* in_sizes, int n_in,
                              void* d_out, int out_size) {
    const float* of    = (const float*)d_in[0];
    const float* cls   = (const float*)d_in[1];
    const float* W1    = (const float*)d_in[2];
    const float* b1    = (const float*)d_in[3];
    const float* gamma = (const float*)d_in[4];
    const float* beta  = (const float*)d_in[5];
    const float* rm    = (const float*)d_in[6];
    const float* rv    = (const float*)d_in[7];
    const float* W2    = (const float*)d_in[8];
    const float* b2    = (const float*)d_in[9];
    const float* Wa    = (const float*)d_in[10];

    float* out    = (float*)d_out;
    float* F      = out;                                   // [PAIRS, OUT]
    float* enh    = out + (size_t)PAIRS * OUT_DIM;         // [NN, OUT]
    float* clsout = enh + (size_t)NN * OUT_DIM;            // [PAIRS, CLS_DIM]

    cudaFuncSetAttribute(gemm1_mma, cudaFuncAttributeMaxDynamicSharedMemorySize, SMEM_GEMM);
    cudaFuncSetAttribute(gemm2_mma, cudaFuncAttributeMaxDynamicSharedMemorySize, SMEM_GEMM);

    cudaMemcpyAsync(clsout, cls, (size_t)PAIRS * CLS_DIM * sizeof(float),
                    cudaMemcpyDeviceToDevice, 0);

    precompute_pij<<<(2 * NN * HID) / 256, 256>>>(of, W1, b1);
    conv_cls<<<(PAIRS * CLS_DIM / 4) / 256, 256>>>(cls);
    conv_w1c<<<(HID * CLS_DIM) / 256, 256>>>(W1);
    conv_w2s<<<(OUT_DIM * HID) / 256, 256>>>(gamma, rv, W2);
    prep_b2p<<<OUT_DIM, 128>>>(gamma, beta, rm, rv, W2, b2);

    dim3 g1(HID / 128, PAIRS / 128);        // x = n-tile (fast), y = m-tile
    gemm1_mma<<<g1, 256, SMEM_GEMM>>>();

    dim3 g2(OUT_DIM / 128, PAIRS / 128);
    gemm2_mma<<<g2, 256, SMEM_GEMM>>>(F);

    softmax_enhance<<<NN, 256>>>(F, Wa, enh);
}

// round 12
// speedup vs baseline: 3.2138x; 1.3019x over previous
#include <cuda_runtime.h>
#include <cuda_fp16.h>
#include <stdint.h>
#include <math.h>

#define NN      384
#define PAIRS   (NN*NN)          // 147456
#define IN_DIM  256
#define CLS_DIM 128
#define HID     512
#define OUT_DIM 256
#define FAN1    640
#define BN_EPS  1e-5f

// ---------------- device scratch ---------------------------------------------------
__device__ __align__(16) float g_Pi[NN * HID];
__device__ __align__(16) float g_Pj[NN * HID];
__device__ __align__(16) float g_b2p[OUT_DIM];
__device__ __align__(16) __half g_Ch[(size_t)PAIRS * CLS_DIM];    // cls fp16
__device__ __align__(16) __half g_W1h[HID * CLS_DIM];             // W1c fp16
__device__ __align__(16) __half g_W2h[OUT_DIM * HID];             // (W2*s) fp16
__device__ __align__(16) __half g_Hh[(size_t)PAIRS * HID];        // lrelu(H) fp16

// ---------------- helpers ----------------------------------------------------------

__device__ __forceinline__ uint32_t smem_u32(const void* p) {
    uint32_t a;
    asm("{ .reg .u64 t; cvta.to.shared.u64 t, %1; cvt.u32.u64 %0, t; }" : "=r"(a) : "l"(p));
    return a;
}

#define CP_ASYNC16(s, g) \
    asm volatile("cp.async.cg.shared.global [%0], [%1], 16;" :: "r"(s), "l"(g) : "memory")
#define CP_COMMIT()   asm volatile("cp.async.commit_group;" ::: "memory")
#define CP_WAIT(n)    asm volatile("cp.async.wait_group %0;" :: "n"(n) : "memory")

#define LDMATRIX_X4(r0, r1, r2, r3, addr) \
    asm volatile("ldmatrix.sync.aligned.m8n8.x4.shared.b16 {%0,%1,%2,%3}, [%4];" \
        : "=r"(r0), "=r"(r1), "=r"(r2), "=r"(r3) : "r"(addr))

#define MMA_F16(c, a, b) \
    asm volatile("mma.sync.aligned.m16n8k16.row.col.f32.f16.f16.f32 " \
        "{%0,%1,%2,%3}, {%4,%5,%6,%7}, {%8,%9}, {%0,%1,%2,%3};" \
        : "+f"((c)[0]), "+f"((c)[1]), "+f"((c)[2]), "+f"((c)[3]) \
        : "r"((a)[0]), "r"((a)[1]), "r"((a)[2]), "r"((a)[3]), "r"((b)[0]), "r"((b)[1]))

// smem: 2 stages x (A 16K | B 16K) = 64KB
#define TILE_BYTES  16384
#define STAGE_BYTES 32768
#define SMEM_GEMM   65536

// per-stage loader: 2 tiles of [128 rows x 64 fp16], SW128 chunk swizzle
#define LOAD_STAGE(sa, Ap, Bp, strideA, strideB, kc) do {                             \
    _Pragma("unroll")                                                                 \
    for (int it = 0; it < 4; ++it) {                                                  \
        int idx = tid + it * 256, r = idx >> 3, c = idx & 7;                          \
        uint32_t sw = r * 128 + ((c ^ (r & 7)) << 4);                                 \
        CP_ASYNC16((sa) + sw,              (Ap) + (size_t)(m0 + r) * (strideA) + (kc) + c * 8); \
        CP_ASYNC16((sa) + TILE_BYTES + sw, (Bp) + (size_t)(n0 + r) * (strideB) + (kc) + c * 8); \
    }                                                                                 \
} while (0)

#define COMPUTE_STAGE(stage_base) do {                                                \
    uint32_t saw = (stage_base) + (wm * 64) * 128;                                    \
    uint32_t sbw = (stage_base) + TILE_BYTES + (wn * 32) * 128;                       \
    _Pragma("unroll")                                                                 \
    for (int ks = 0; ks < 4; ++ks) {                                                  \
        uint32_t b[4][2];                                                             \
        _Pragma("unroll")                                                             \
        for (int np = 0; np < 2; ++np) {                                              \
            int nrow = np * 16 + (lane & 7) + ((lane >> 4) << 3);                     \
            int cc = ks * 2 + ((lane >> 3) & 1);                                      \
            uint32_t addr = sbw + nrow * 128 + ((cc ^ (nrow & 7)) << 4);              \
            LDMATRIX_X4(b[np*2][0], b[np*2][1], b[np*2+1][0], b[np*2+1][1], addr);    \
        }                                                                             \
        _Pragma("unroll")                                                             \
        for (int mt = 0; mt < 4; ++mt) {                                              \
            int row = mt * 16 + (lane & 15);                                          \
            int cc = ks * 2 + (lane >> 4);                                            \
            uint32_t addr = saw + row * 128 + ((cc ^ (row & 7)) << 4);                \
            uint32_t a[4];                                                            \
            LDMATRIX_X4(a[0], a[1], a[2], a[3], addr);                                \
            _Pragma("unroll")                                                         \
            for (int nt = 0; nt < 4; ++nt) MMA_F16(acc[mt][nt], a, b[nt]);            \
        }                                                                             \
    }                                                                                 \
} while (0)

// ---------------- precompute / conversion kernels ----------------------------------

__global__ void precompute_pij(const float* __restrict__ of,
                               const float* __restrict__ W1,
                               const float* __restrict__ b1) {
    int idx = blockIdx.x * blockDim.x + threadIdx.x;
    const int half = NN * HID;
    bool isPi = idx < half;
    int t = isPi ? idx : idx - half;
    int i = t / HID, h = t - (t / HID) * HID;
    const float* a = of + (size_t)i * IN_DIM;
    const float* w = W1 + (size_t)h * FAN1 + (isPi ? 0 : IN_DIM);
    float acc = 0.f;
#pragma unroll 8
    for (int k = 0; k < IN_DIM; k += 4) {
        float4 av = *(const float4*)(a + k);
        float4 wv = *(const float4*)(w + k);
        acc = fmaf(av.x, wv.x, acc);
        acc = fmaf(av.y, wv.y, acc);
        acc = fmaf(av.z, wv.z, acc);
        acc = fmaf(av.w, wv.w, acc);
    }
    if (isPi) g_Pi[t] = acc + b1[h];
    else      g_Pj[t] = acc;
}

__global__ void conv_cls(const float* __restrict__ cls) {
    size_t q = (size_t)blockIdx.x * 256 + threadIdx.x;       // quad of 4 floats
    float4 v = ((const float4*)cls)[q];
    __align__(8) __half hh[4];
    hh[0] = __float2half_rn(v.x); hh[1] = __float2half_rn(v.y);
    hh[2] = __float2half_rn(v.z); hh[3] = __float2half_rn(v.w);
    *(uint2*)(g_Ch + q * 4) = *(uint2*)hh;
}

__global__ void conv_w1c(const float* __restrict__ W1) {
    int idx = blockIdx.x * 256 + threadIdx.x;                // HID*CLS_DIM
    int h = idx >> 7, k = idx & 127;
    g_W1h[idx] = __float2half_rn(W1[(size_t)h * FAN1 + 512 + k]);
}

__global__ void conv_w2s(const float* __restrict__ gamma,
                         const float* __restrict__ rv,
                         const float* __restrict__ W2) {
    int idx = blockIdx.x * 256 + threadIdx.x;                // OUT_DIM*HID
    int h = idx & (HID - 1);
    float s = gamma[h] * rsqrtf(rv[h] + BN_EPS);
    g_W2h[idx] = __float2half_rn(W2[idx] * s);
}

__global__ void prep_b2p(const float* __restrict__ gamma,
                         const float* __restrict__ beta,
                         const float* __restrict__ rm,
                         const float* __restrict__ rv,
                         const float* __restrict__ W2,
                         const float* __restrict__ b2) {
    __shared__ float red[4];
    int o = blockIdx.x, t = threadIdx.x;
    float acc = 0.f;
    for (int h = t; h < HID; h += 128) {
        float s = gamma[h] * rsqrtf(rv[h] + BN_EPS);
        acc = fmaf(beta[h] - rm[h] * s, W2[(size_t)o * HID + h], acc);
    }
#pragma unroll
    for (int s = 16; s; s >>= 1) acc += __shfl_xor_sync(0xffffffffu, acc, s);
    if ((t & 31) == 0) red[t >> 5] = acc;
    __syncthreads();
    if (t == 0) g_b2p[o] = red[0] + red[1] + red[2] + red[3] + b2[o];
}

// ---------------- GEMM1: H = lrelu(cls@W1c.T + Pi + Pj) -> fp16 --------------------
// grid (HID/128 = 4, PAIRS/128 = 1152). 2 K-chunks of 64.

__global__ __launch_bounds__(256) void gemm1_mma() {
    extern __shared__ char smem[];
    const uint32_t sb = smem_u32(smem);
    const int tid = threadIdx.x, lane = tid & 31, wid = tid >> 5;
    const int wm = wid & 1, wn = wid >> 1;
    const int m0 = blockIdx.y * 128, n0 = blockIdx.x * 128;

    float acc[4][4][4];
#pragma unroll
    for (int a = 0; a < 4; a++)
#pragma unroll
        for (int b = 0; b < 4; b++)
#pragma unroll
            for (int c = 0; c < 4; c++) acc[a][b][c] = 0.f;

    LOAD_STAGE(sb, g_Ch, g_W1h, CLS_DIM, CLS_DIM, 0);
    CP_COMMIT();

#pragma unroll
    for (int iter = 0; iter < 2; ++iter) {
        uint32_t stage = sb + (iter & 1) * STAGE_BYTES;
        if (iter + 1 < 2) {
            uint32_t nstage = sb + ((iter + 1) & 1) * STAGE_BYTES;
            LOAD_STAGE(nstage, g_Ch, g_W1h, CLS_DIM, CLS_DIM, (iter + 1) * 64);
            CP_COMMIT();
            CP_WAIT(1);
        } else CP_WAIT(0);
        __syncthreads();
        COMPUTE_STAGE(stage);
        __syncthreads();
    }

    // epilogue: + Pi + Pj, lrelu, fp16 store
#pragma unroll
    for (int mt = 0; mt < 4; ++mt) {
#pragma unroll
        for (int half = 0; half < 2; ++half) {
            int r = wm * 64 + mt * 16 + (lane >> 2) + half * 8;
            int m = m0 + r;
            int i = m / NN, j = m - (m / NN) * NN;
#pragma unroll
            for (int nt = 0; nt < 4; ++nt) {
                int h = n0 + wn * 32 + nt * 8 + 2 * (lane & 3);
                float2 pi = *(const float2*)(g_Pi + (size_t)i * HID + h);
                float2 pj = *(const float2*)(g_Pj + (size_t)j * HID + h);
                float v0 = acc[mt][nt][half * 2 + 0] + pi.x + pj.x;
                float v1 = acc[mt][nt][half * 2 + 1] + pi.y + pj.y;
                v0 = v0 >= 0.f ? v0 : 0.01f * v0;
                v1 = v1 >= 0.f ? v1 : 0.01f * v1;
                __align__(4) __half hh[2];
                hh[0] = __float2half_rn(v0);
                hh[1] = __float2half_rn(v1);
                *(uint32_t*)(g_Hh + (size_t)m * HID + h) = *(uint32_t*)hh;
            }
        }
    }
}

// ---------------- GEMM2: F = H @ (W2*s).T + b2' ------------------------------------
// grid (OUT/128 = 2, PAIRS/128 = 1152). 8 K-chunks of 64.

__global__ __launch_bounds__(256) void gemm2_mma(float* __restrict__ F) {
    extern __shared__ char smem[];
    const uint32_t sb = smem_u32(smem);
    const int tid = threadIdx.x, lane = tid & 31, wid = tid >> 5;
    const int wm = wid & 1, wn = wid >> 1;
    const int m0 = blockIdx.y * 128, n0 = blockIdx.x * 128;

    float acc[4][4][4];
#pragma unroll
    for (int a = 0; a < 4; a++)
#pragma unroll
        for (int b = 0; b < 4; b++)
#pragma unroll
            for (int c = 0; c < 4; c++) acc[a][b][c] = 0.f;

    LOAD_STAGE(sb, g_Hh, g_W2h, HID, HID, 0);
    CP_COMMIT();

    for (int iter = 0; iter < 8; ++iter) {
        uint32_t stage = sb + (iter & 1) * STAGE_BYTES;
        if (iter + 1 < 8) {
            uint32_t nstage = sb + ((iter + 1) & 1) * STAGE_BYTES;
            LOAD_STAGE(nstage, g_Hh, g_W2h, HID, HID, (iter + 1) * 64);
            CP_COMMIT();
            CP_WAIT(1);
        } else CP_WAIT(0);
        __syncthreads();
        COMPUTE_STAGE(stage);
        __syncthreads();
    }

#pragma unroll
    for (int mt = 0; mt < 4; ++mt) {
#pragma unroll
        for (int half = 0; half < 2; ++half) {
            int r = wm * 64 + mt * 16 + (lane >> 2) + half * 8;
            int m = m0 + r;
#pragma unroll
            for (int nt = 0; nt < 4; ++nt) {
                int o = n0 + wn * 32 + nt * 8 + 2 * (lane & 3);
                float2 bb = *(const float2*)(g_b2p + o);
                float2 v;
                v.x = acc[mt][nt][half * 2 + 0] + bb.x;
                v.y = acc[mt][nt][half * 2 + 1] + bb.y;
                *(float2*)(F + (size_t)m * OUT_DIM + o) = v;
            }
        }
    }
}

// ---------------- softmax over j + weighted pooling --------------------------------

__global__ __launch_bounds__(256) void softmax_enhance(const float* __restrict__ F,
                                                       const float* __restrict__ Wa,
                                                       float* __restrict__ enhanced) {
    const int i = blockIdx.x;
    __shared__ float logit[NN];
    __shared__ float redm[8];
    __shared__ float reds[8];
    const int tid = threadIdx.x;
    const int lane = tid & 31, w = tid >> 5;

    for (int j = w; j < NN; j += 8) {
        const float* f = F + ((size_t)i * NN + j) * OUT_DIM;
        float p = 0.f;
        for (int o = lane; o < OUT_DIM; o += 32) p = fmaf(f[o], Wa[o], p);
#pragma unroll
        for (int s = 16; s; s >>= 1) p += __shfl_xor_sync(0xffffffffu, p, s);
        if (lane == 0) logit[j] = p;
    }
    __syncthreads();

    float m = -1e30f;
    for (int j = tid; j < NN; j += 256) m = fmaxf(m, logit[j]);
#pragma unroll
    for (int s = 16; s; s >>= 1) m = fmaxf(m, __shfl_xor_sync(0xffffffffu, m, s));
    if (lane == 0) redm[w] = m;
    __syncthreads();
    float M = fmaxf(fmaxf(fmaxf(redm[0], redm[1]), fmaxf(redm[2], redm[3])),
                    fmaxf(fmaxf(redm[4], redm[5]), fmaxf(redm[6], redm[7])));

    float sacc = 0.f;
    for (int j = tid; j < NN; j += 256) {
        float e = expf(logit[j] - M);
        logit[j] = e;
        sacc += e;
    }
#pragma unroll
    for (int s = 16; s; s >>= 1) sacc += __shfl_xor_sync(0xffffffffu, sacc, s);
    if (lane == 0) reds[w] = sacc;
    __syncthreads();
    float S = reds[0] + reds[1] + reds[2] + reds[3] + reds[4] + reds[5] + reds[6] + reds[7];
    float inv = 1.f / S;
    __syncthreads();

    const int o = tid;
    float acc = 0.f;
    const float* fb = F + (size_t)i * NN * OUT_DIM + o;
#pragma unroll 4
    for (int j = 0; j < NN; j++) acc = fmaf(logit[j], fb[(size_t)j * OUT_DIM], acc);
    enhanced[(size_t)i * OUT_DIM + o] = acc * inv;
}

// ---------------- launch -----------------------------------------------------------

extern "C" void kernel_launch(void* const* d_in, const int* in_sizes, int n_in,
                              void* d_out, int out_size) {
    const float* of    = (const float*)d_in[0];
    const float* cls   = (const float*)d_in[1];
    const float* W1    = (const float*)d_in[2];
    const float* b1    = (const float*)d_in[3];
    const float* gamma = (const float*)d_in[4];
    const float* beta  = (const float*)d_in[5];
    const float* rm    = (const float*)d_in[6];
    const float* rv    = (const float*)d_in[7];
    const float* W2    = (const float*)d_in[8];
    const float* b2    = (const float*)d_in[9];
    const float* Wa    = (const float*)d_in[10];

    float* out    = (float*)d_out;
    float* F      = out;                                   // [PAIRS, OUT]
    float* enh    = out + (size_t)PAIRS * OUT_DIM;         // [NN, OUT]
    float* clsout = enh + (size_t)NN * OUT_DIM;            // [PAIRS, CLS_DIM]

    cudaFuncSetAttribute(gemm1_mma, cudaFuncAttributeMaxDynamicSharedMemorySize, SMEM_GEMM);
    cudaFuncSetAttribute(gemm2_mma, cudaFuncAttributeMaxDynamicSharedMemorySize, SMEM_GEMM);

    cudaMemcpyAsync(clsout, cls, (size_t)PAIRS * CLS_DIM * sizeof(float),
                    cudaMemcpyDeviceToDevice, 0);

    precompute_pij<<<(2 * NN * HID) / 256, 256>>>(of, W1, b1);
    conv_cls<<<(PAIRS * CLS_DIM / 4) / 256, 256>>>(cls);
    conv_w1c<<<(HID * CLS_DIM) / 256, 256>>>(W1);
    conv_w2s<<<(OUT_DIM * HID) / 256, 256>>>(gamma, rv, W2);
    prep_b2p<<<OUT_DIM, 128>>>(gamma, beta, rm, rv, W2, b2);

    dim3 g1(HID / 128, PAIRS / 128);        // x = n-tile (fast), y = m-tile
    gemm1_mma<<<g1, 256, SMEM_GEMM>>>();

    dim3 g2(OUT_DIM / 128, PAIRS / 128);
    gemm2_mma<<<g2, 256, SMEM_GEMM>>>(F);

    softmax_enhance<<<NN, 256>>>(F, Wa, enh);
}